// round 11
// baseline (speedup 1.0000x reference)
#include <cuda_runtime.h>
#include <cstdint>

#define NB     8
#define NPOS   21824
#define NG     (NPOS / 4)
#define NCLS   80
#define KTOP   1000
#define NBIN   8192
#define CAP    2048
#define IOU_TH 0.5f
#define MPITCH 33

// ---------------- scratch ----------------
__device__ __align__(16) float g_score[NB * NPOS];
__device__ __align__(16) int   g_kind [NB * NPOS];
__device__ float4              g_boxes[NB * NPOS];
__device__ unsigned            g_hist [NB * NBIN];     // zero at load; k_thresh re-zeros
__device__ int                 g_thresh[NB];
__device__ int                 g_cnt  [NB];
__device__ unsigned long long  g_cand [NB * CAP];
__device__ float4              g_topBox  [NB * KTOP];
__device__ int                 g_topKind [NB * KTOP];
__device__ float               g_topScore[NB * KTOP];

// ---------------- K1: decode, 4-way class-split per position quad ------------
__global__ void k_decode(
    const float* __restrict__ c0, const float* __restrict__ c1,
    const float* __restrict__ c2, const float* __restrict__ c3,
    const float* __restrict__ c4,
    const float* __restrict__ r0, const float* __restrict__ r1,
    const float* __restrict__ r2, const float* __restrict__ r3,
    const float* __restrict__ r4)
{
    int tix = blockIdx.x * blockDim.x + threadIdx.x;   // 0..22015
    int g   = tix >> 2;                                 // position quad
    int r   = tix & 3;                                  // class-chunk lane
    bool valid = (g < NG);
    if (!valid) g = NG - 1;                             // clamp; keep lanes for shfl
    int b   = blockIdx.y;
    int pos = g << 2;

    int lvl, local, logw;
    float stride;
    if      (pos < 16384) { lvl = 0; local = pos;         logw = 7; stride = 8.f;   }
    else if (pos < 20480) { lvl = 1; local = pos - 16384; logw = 6; stride = 16.f;  }
    else if (pos < 21504) { lvl = 2; local = pos - 20480; logw = 5; stride = 32.f;  }
    else if (pos < 21760) { lvl = 3; local = pos - 21504; logw = 4; stride = 64.f;  }
    else                  { lvl = 4; local = pos - 21760; logw = 3; stride = 128.f; }
    int hw    = 1 << (2 * logw);
    int cstep = hw >> 2;

    const float* clsA[5] = { c0, c1, c2, c3, c4 };
    const float* regA[5] = { r0, r1, r2, r3, r4 };

    // classes [20r, 20r+20)
    const float4* cls = (const float4*)(clsA[lvl] + (size_t)b * NCLS * hw + local)
                        + (size_t)(r * 20) * cstep;
    float4 bv = cls[0];
    int k0 = r * 20, k1 = k0, k2 = k0, k3 = k0;
    #pragma unroll
    for (int c = 1; c < 20; c++) {
        float4 v = cls[(size_t)c * cstep];
        int kc = r * 20 + c;
        if (v.x > bv.x) { bv.x = v.x; k0 = kc; }
        if (v.y > bv.y) { bv.y = v.y; k1 = kc; }
        if (v.z > bv.z) { bv.z = v.z; k2 = kc; }
        if (v.w > bv.w) { bv.w = v.w; k3 = kc; }
    }

    // quad reduction: max value, lowest class on ties (scores >= 0)
    unsigned long long p0 = ((unsigned long long)__float_as_uint(bv.x) << 32) | (unsigned)(255 - k0);
    unsigned long long p1 = ((unsigned long long)__float_as_uint(bv.y) << 32) | (unsigned)(255 - k1);
    unsigned long long p2 = ((unsigned long long)__float_as_uint(bv.z) << 32) | (unsigned)(255 - k2);
    unsigned long long p3 = ((unsigned long long)__float_as_uint(bv.w) << 32) | (unsigned)(255 - k3);
    #pragma unroll
    for (int off = 1; off <= 2; off <<= 1) {
        unsigned long long q;
        q = __shfl_xor_sync(0xFFFFFFFFu, p0, off); if (q > p0) p0 = q;
        q = __shfl_xor_sync(0xFFFFFFFFu, p1, off); if (q > p1) p1 = q;
        q = __shfl_xor_sync(0xFFFFFFFFu, p2, off); if (q > p2) p2 = q;
        q = __shfl_xor_sync(0xFFFFFFFFu, p3, off); if (q > p3) p3 = q;
    }

    if (r == 0 && valid) {
        float m0 = __uint_as_float((unsigned)(p0 >> 32));
        float m1 = __uint_as_float((unsigned)(p1 >> 32));
        float m2 = __uint_as_float((unsigned)(p2 >> 32));
        float m3 = __uint_as_float((unsigned)(p3 >> 32));
        int  c0i = 255 - (int)(p0 & 0xFFu);
        int  c1i = 255 - (int)(p1 & 0xFFu);
        int  c2i = 255 - (int)(p2 & 0xFFu);
        int  c3i = 255 - (int)(p3 & 0xFFu);

        const float4* rg = (const float4*)(regA[lvl] + (size_t)b * 4 * hw + local);
        float4 dl4 = rg[0];
        float4 dt4 = rg[cstep];
        float4 dr4 = rg[2 * cstep];
        float4 db4 = rg[3 * cstep];

        int w = 1 << logw;
        int y = local >> logw;
        int x = local & (w - 1);
        float cy = ((float)y + 0.5f) * stride;

        int o = b * NPOS + pos;
        float cx = ((float)(x + 0) + 0.5f) * stride;
        g_boxes[o + 0] = make_float4(cx - dl4.x * stride, cy - dt4.x * stride,
                                     cx + dr4.x * stride, cy + db4.x * stride);
        cx = ((float)(x + 1) + 0.5f) * stride;
        g_boxes[o + 1] = make_float4(cx - dl4.y * stride, cy - dt4.y * stride,
                                     cx + dr4.y * stride, cy + db4.y * stride);
        cx = ((float)(x + 2) + 0.5f) * stride;
        g_boxes[o + 2] = make_float4(cx - dl4.z * stride, cy - dt4.z * stride,
                                     cx + dr4.z * stride, cy + db4.z * stride);
        cx = ((float)(x + 3) + 0.5f) * stride;
        g_boxes[o + 3] = make_float4(cx - dl4.w * stride, cy - dt4.w * stride,
                                     cx + dr4.w * stride, cy + db4.w * stride);

        float s0 = (m0 > 0.05f) ? m0 : 0.0f;
        float s1 = (m1 > 0.05f) ? m1 : 0.0f;
        float s2 = (m2 > 0.05f) ? m2 : 0.0f;
        float s3 = (m3 > 0.05f) ? m3 : 0.0f;
        *(float4*)&g_score[o] = make_float4(s0, s1, s2, s3);
        *(int4*)&g_kind[o]    = make_int4(c0i, c1i, c2i, c3i);

        unsigned* hb = &g_hist[b * NBIN];
        if (s0 > 0.0f) { int bn = (int)(s0 * (float)NBIN); if (bn > NBIN-1) bn = NBIN-1; atomicAdd(&hb[bn], 1u); }
        if (s1 > 0.0f) { int bn = (int)(s1 * (float)NBIN); if (bn > NBIN-1) bn = NBIN-1; atomicAdd(&hb[bn], 1u); }
        if (s2 > 0.0f) { int bn = (int)(s2 * (float)NBIN); if (bn > NBIN-1) bn = NBIN-1; atomicAdd(&hb[bn], 1u); }
        if (s3 > 0.0f) { int bn = (int)(s3 * (float)NBIN); if (bn > NBIN-1) bn = NBIN-1; atomicAdd(&hb[bn], 1u); }
    }
}

// ---------------- K2: k_thresh — per-image threshold bin; reset scratch ------
__global__ void __launch_bounds__(1024) k_thresh()
{
    const int b   = blockIdx.x;
    const int tid = threadIdx.x;

    __shared__ unsigned hcopy[NBIN];    // 32 KB
    __shared__ unsigned gsum[1024];
    __shared__ unsigned ssum[32];

    unsigned* hb = &g_hist[b * NBIN];
    {
        unsigned s = 0;
        #pragma unroll
        for (int r = 0; r < 8; r++) {
            unsigned h = hb[NBIN - 1 - (8 * tid + r)];
            hcopy[NBIN - 1 - (8 * tid + r)] = h;
            s += h;
        }
        gsum[tid] = s;
    }
    __syncthreads();
    if (tid < 32) {
        unsigned s = 0;
        #pragma unroll
        for (int q = 0; q < 32; q++) s += gsum[tid * 32 + q];
        ssum[tid] = s;
    }
    __syncthreads();
    if (tid == 0) {
        unsigned cum = 0;
        int t = 0;
        bool found = false;
        for (int w = 0; w < 32 && !found; w++) {
            if (cum + ssum[w] < KTOP) { cum += ssum[w]; continue; }
            for (int g = w * 32; g < w * 32 + 32 && !found; g++) {
                if (cum + gsum[g] < KTOP) { cum += gsum[g]; continue; }
                for (int r = g * 8; r < g * 8 + 8; r++) {
                    cum += hcopy[NBIN - 1 - r];
                    if (cum >= KTOP) { t = NBIN - 1 - r; found = true; break; }
                }
            }
        }
        g_thresh[b] = found ? t : 0;
        g_cnt[b]    = 0;
    }
    __syncthreads();
    for (int i = tid; i < NBIN; i += 1024) hb[i] = 0u;   // ready for next replay
}

// ---------------- K3: k_compact — distributed candidate compaction -----------
__global__ void k_compact()
{
    int idx4 = blockIdx.x * blockDim.x + threadIdx.x;
    if (idx4 >= NG) return;
    int b = blockIdx.y;
    int t = g_thresh[b];

    float4 s4 = *(const float4*)&g_score[b * NPOS + (idx4 << 2)];
    #pragma unroll
    for (int c = 0; c < 4; c++) {
        float sc = (c == 0) ? s4.x : (c == 1) ? s4.y : (c == 2) ? s4.z : s4.w;
        if (sc > 0.0f) {
            int bin = (int)(sc * (float)NBIN);
            if (bin > NBIN - 1) bin = NBIN - 1;
            if (bin >= t) {
                int k = atomicAdd(&g_cnt[b], 1);
                if (k < CAP) {
                    unsigned i = (unsigned)((idx4 << 2) + c);
                    g_cand[b * CAP + k] =
                        ((unsigned long long)__float_as_uint(sc) << 32) |
                        (unsigned long long)(0xFFFFFFFFu - i);
                }
            }
        }
    }
}

// ---------------- K4: k_select — counting sort of candidates + emit ----------
// smem: buf u64[2048] | buf2 u64[2048] | fineH u32[8192] | offs u32[8192]
#define SEL_BUF2  16384
#define SEL_FH    32768
#define SEL_OFF   65536
#define SEL_SMEM  98304

__global__ void __launch_bounds__(1024) k_select(float* __restrict__ out)
{
    const int b   = blockIdx.x;
    const int tid = threadIdx.x;

    extern __shared__ char sm[];
    unsigned long long* buf   = (unsigned long long*)sm;
    unsigned long long* buf2  = (unsigned long long*)(sm + SEL_BUF2);
    unsigned*           fineH = (unsigned*)(sm + SEL_FH);
    unsigned*           offs  = (unsigned*)(sm + SEL_OFF);

    __shared__ unsigned sWarp[32];

    const int   t     = g_thresh[b];
    const int   C     = min(g_cnt[b], CAP);
    const float lo    = (float)t * (1.0f / (float)NBIN);
    const float scale = (float)NBIN / (1.0f - lo + 1e-6f);

    for (int i = tid; i < NBIN; i += 1024) fineH[i] = 0u;
    __syncthreads();

    // load keys + fine histogram
    for (int k = tid; k < C; k += 1024) {
        unsigned long long key = g_cand[b * CAP + k];
        buf[k] = key;
        float sc = __uint_as_float((unsigned)(key >> 32));
        int fb = (int)((sc - lo) * scale);
        fb = max(0, min(NBIN - 1, fb));
        atomicAdd(&fineH[fb], 1u);
    }
    __syncthreads();

    // exclusive scan over fine bins, descending
    unsigned c8[8];
    unsigned tsum = 0;
    #pragma unroll
    for (int r = 0; r < 8; r++) {
        int fb = NBIN - 1 - (tid * 8 + r);
        c8[r] = fineH[fb];
        tsum += c8[r];
    }
    {
        unsigned lane = tid & 31, wrp = tid >> 5;
        unsigned v = tsum;
        #pragma unroll
        for (int o = 1; o < 32; o <<= 1) {
            unsigned u = __shfl_up_sync(0xFFFFFFFFu, v, o);
            if (lane >= o) v += u;
        }
        unsigned wexcl = v - tsum;
        if (lane == 31) sWarp[wrp] = v;
        __syncthreads();
        if (tid < 32) {
            unsigned w0 = sWarp[tid];
            unsigned vv = w0;
            #pragma unroll
            for (int o = 1; o < 32; o <<= 1) {
                unsigned u = __shfl_up_sync(0xFFFFFFFFu, vv, o);
                if (tid >= (unsigned)o) vv += u;
            }
            sWarp[tid] = vv - w0;
        }
        __syncthreads();
        unsigned run = sWarp[wrp] + wexcl;
        #pragma unroll
        for (int r = 0; r < 8; r++) {
            int fb = NBIN - 1 - (tid * 8 + r);
            offs[fb] = run;
            run += c8[r];
        }
    }
    __syncthreads();

    // scatter
    for (int k = tid; k < C; k += 1024) {
        unsigned long long key = buf[k];
        float sc = __uint_as_float((unsigned)(key >> 32));
        int fb = (int)((sc - lo) * scale);
        fb = max(0, min(NBIN - 1, fb));
        unsigned slot = atomicAdd(&offs[fb], 1u);
        buf2[slot] = key;
    }
    __syncthreads();

    // intra-bin fixups
    for (int fb = tid; fb < NBIN; fb += 1024) {
        unsigned c = fineH[fb];
        if (c >= 2) {
            unsigned st = offs[fb] - c;
            for (unsigned a = st + 1; a < st + c; a++) {
                unsigned long long kv = buf2[a];
                unsigned p = a;
                while (p > st && buf2[p - 1] < kv) { buf2[p] = buf2[p - 1]; p--; }
                buf2[p] = kv;
            }
        }
    }
    __syncthreads();

    // emit cols 0..4 + stage NMS inputs
    if (tid < KTOP) {
        int i = tid;
        unsigned long long key = (i < C) ? buf2[i] : 0ULL;
        unsigned pos = 0xFFFFFFFFu - (unsigned)(key & 0xFFFFFFFFull);
        if (key == 0ULL) pos = 0;
        int src = b * NPOS + (int)pos;
        float4 bx = g_boxes[src];
        int    kd = g_kind[src];

        int row = b * KTOP + i;
        out[row * 6 + 0] = bx.x;
        out[row * 6 + 1] = bx.y;
        out[row * 6 + 2] = bx.z;
        out[row * 6 + 3] = bx.w;
        out[row * 6 + 4] = (float)kd;

        g_topBox[row]   = bx;
        g_topKind[row]  = kd;
        g_topScore[row] = (key != 0ULL) ? __uint_as_float((unsigned)(key >> 32)) : 0.0f;
    }
}

// ---------------- K5: k_nms — mask build + Jacobi fixpoint greedy ------------
#define NMS_X1  132000
#define NMS_Y1  136000
#define NMS_X2  140000
#define NMS_Y2  144000
#define NMS_AR  148000
#define NMS_KD  152000
#define NMS_NZ  156000
#define NMS_KB  160000
#define NMS_SMEM 170240

__global__ void __launch_bounds__(1024) k_nms(float* __restrict__ out)
{
    const int b    = blockIdx.x;
    const int tid  = threadIdx.x;
    const int wid  = tid >> 5;
    const int lane = tid & 31;

    extern __shared__ char sm[];
    unsigned* mask     = (unsigned*)sm;
    float*    sx1      = (float*)(sm + NMS_X1);
    float*    sy1      = (float*)(sm + NMS_Y1);
    float*    sx2      = (float*)(sm + NMS_X2);
    float*    sy2      = (float*)(sm + NMS_Y2);
    float*    sar      = (float*)(sm + NMS_AR);
    int*      skd      = (int*)(sm + NMS_KD);
    unsigned* rowNZ    = (unsigned*)(sm + NMS_NZ);
    unsigned* kindBits = (unsigned*)(sm + NMS_KB);

    __shared__ unsigned remA[32], remB[32];
    __shared__ int s_changed;

    for (int i = tid; i < NCLS * 32; i += 1024) kindBits[i] = 0u;
    if (tid < KTOP) rowNZ[tid] = 0u;
    if (tid < 32) remA[tid] = 0u;
    __syncthreads();

    if (tid < KTOP) {
        int i = tid;
        int row = b * KTOP + i;
        float4 bx = g_topBox[row];
        int kd    = g_topKind[row];
        sx1[i] = bx.x; sy1[i] = bx.y; sx2[i] = bx.z; sy2[i] = bx.w;
        sar[i] = fmaxf(bx.z - bx.x, 0.0f) * fmaxf(bx.w - bx.y, 0.0f);
        skd[i] = kd;
        atomicOr(&kindBits[kd * 32 + (i >> 5)], 1u << (i & 31));
    }
    __syncthreads();

    for (int task = tid; task < KTOP * 32; task += 1024) {
        int i = task >> 5;
        int w = task & 31;
        int kd = skd[i];
        unsigned cand = kindBits[kd * 32 + w];
        int iw = i >> 5;
        if (w < iw)       cand = 0u;
        else if (w == iw) cand &= ~((2u << (i & 31)) - 1u);
        unsigned bits = 0u;
        if (cand) {
            float x1 = sx1[i], y1 = sy1[i], x2 = sx2[i], y2 = sy2[i], ai = sar[i];
            do {
                int jj = __ffs(cand) - 1;
                cand &= cand - 1u;
                int j = w * 32 + jj;
                float xx1 = fmaxf(x1, sx1[j]);
                float yy1 = fmaxf(y1, sy1[j]);
                float xx2 = fminf(x2, sx2[j]);
                float yy2 = fminf(y2, sy2[j]);
                float inter = fmaxf(xx2 - xx1, 0.0f) * fmaxf(yy2 - yy1, 0.0f);
                float iou = inter / (((ai + sar[j]) - inter) + 1e-9f);
                if (iou > IOU_TH) bits |= (1u << jj);
            } while (cand);
        }
        mask[i * MPITCH + w] = bits;
        if (bits) rowNZ[i] = 1u;
    }
    __syncthreads();

    for (int round = 0; round < KTOP; round++) {
        if (tid < 32) remB[tid] = 0u;
        if (tid == 0) s_changed = 0;
        __syncthreads();
        for (int r = wid; r < KTOP; r += 32) {
            if (rowNZ[r] && !((remA[r >> 5] >> (r & 31)) & 1u)) {
                unsigned mw = mask[r * MPITCH + lane];
                if (mw) atomicOr(&remB[lane], mw);
            }
        }
        __syncthreads();
        if (tid < 32 && remB[tid] != remA[tid]) s_changed = 1;
        __syncthreads();
        if (!s_changed) break;
        if (tid < 32) remA[tid] = remB[tid];
        __syncthreads();
    }

    if (tid < KTOP) {
        int i = tid;
        bool kept = !((remA[i >> 5] >> (i & 31)) & 1u);
        float sc = g_topScore[b * KTOP + i];
        out[(b * KTOP + i) * 6 + 5] = (kept && sc > 0.0f) ? sc : 0.0f;
    }
}

// ---------------- launch ----------------
extern "C" void kernel_launch(void* const* d_in, const int* in_sizes, int n_in,
                              void* d_out, int out_size)
{
    static const int hw[5] = { 16384, 4096, 1024, 256, 64 };
    const float* clsP[5] = { 0, 0, 0, 0, 0 };
    const float* regP[5] = { 0, 0, 0, 0, 0 };
    bool cntSeen[5] = { false, false, false, false, false };

    for (int i = 0; i < n_in; i++) {
        long long s = in_sizes[i];
        bool matched = false;
        for (int l = 0; l < 5 && !matched; l++)
            if (s == (long long)NB * NCLS * hw[l]) { clsP[l] = (const float*)d_in[i]; matched = true; }
        if (matched) continue;
        for (int l = 0; l < 5 && !matched; l++)
            if (s == (long long)NB * hw[l] && !cntSeen[l]) { cntSeen[l] = true; matched = true; }
        if (matched) continue;
        for (int l = 0; l < 5 && !matched; l++)
            if (s == (long long)NB * 4 * hw[l] && !regP[l]) { regP[l] = (const float*)d_in[i]; matched = true; }
    }

    float* out = (float*)d_out;

    cudaFuncSetAttribute(k_select, cudaFuncAttributeMaxDynamicSharedMemorySize, SEL_SMEM);
    cudaFuncSetAttribute(k_nms,    cudaFuncAttributeMaxDynamicSharedMemorySize, NMS_SMEM);

    dim3 gDec((NPOS + 255) / 256, NB);          // 86 x 8, 256 thr (4 thr/quad)
    k_decode<<<gDec, 256>>>(clsP[0], clsP[1], clsP[2], clsP[3], clsP[4],
                            regP[0], regP[1], regP[2], regP[3], regP[4]);
    k_thresh <<<NB, 1024>>>();
    dim3 gCmp((NG + 255) / 256, NB);            // 22 x 8
    k_compact<<<gCmp, 256>>>();
    k_select <<<NB, 1024, SEL_SMEM>>>(out);
    k_nms    <<<NB, 1024, NMS_SMEM>>>(out);
}

// round 15
// speedup vs baseline: 1.0069x; 1.0069x over previous
#include <cuda_runtime.h>
#include <cstdint>

#define NB     8
#define NPOS   21824
#define NG     (NPOS / 4)
#define NCLS   80
#define KTOP   1000
#define NBIN   8192
#define CAP    2048
#define IOU_TH 0.5f
#define MPITCH 33
#define GRIDX  148          // == resident SM count floor; 1 block/SM guaranteed

// ---------------- scratch ----------------
__device__ __align__(16) float g_score[NB * NPOS];
__device__ __align__(16) int   g_kind [NB * NPOS];
__device__ float4              g_boxes[NB * NPOS];
__device__ unsigned            g_hist [NB * NBIN];     // zero at load; tail re-zeros
__device__ unsigned long long  g_arrive = 0ULL;        // monotonic barrier counter

// smem layout (bytes) for the tail (identical to proven R6 fused layout):
//   [0,     16384)  buf  u64[2048]      unsorted candidate keys
//   [16384, 32768)  buf2 u64[2048]      sorted keys
//   [32768,164768)  mask u32[1000*33]   (after sort; aliases fineH/offs)
//     aliased: [32768,65536) fineH u32[8192]; [65536,98304) offs u32[8192]
//   [164768,188768) sx1/sy1/sx2/sy2/sar f32[1000] + skd i32[1000]
//   [188768,192864) gsum u32[1024] (threshold partials, later row-nonzero flags)
//   [192864,203104) kindBits u32[80*32]
#define SM_BUF2  16384
#define SM_MASK  32768
#define SM_FH    32768
#define SM_OFF   65536
#define SM_X1   164768
#define SM_Y1   168768
#define SM_X2   172768
#define SM_Y2   176768
#define SM_AR   180768
#define SM_KD   184768
#define SM_GS   188768
#define SM_KB   192864
#define SMEM_BYTES 203104

__global__ void __launch_bounds__(1024, 1) k_all(
    const float* __restrict__ c0, const float* __restrict__ c1,
    const float* __restrict__ c2, const float* __restrict__ c3,
    const float* __restrict__ c4,
    const float* __restrict__ r0, const float* __restrict__ r1,
    const float* __restrict__ r2, const float* __restrict__ r3,
    const float* __restrict__ r4,
    float* __restrict__ out)
{
    const int tid = threadIdx.x;

    // ================= part A: decode (all blocks) =================
    {
        const float* clsA[5] = { c0, c1, c2, c3, c4 };
        const float* regA[5] = { r0, r1, r2, r3, r4 };
        const int total  = NB * NPOS;          // lane-tasks (4 lanes per quad)
        const int stride = GRIDX * 1024;

        for (int task = blockIdx.x * 1024 + tid; task < total; task += stride) {
            int q = task >> 2;                  // global quad index
            int r = task & 3;                   // class-chunk lane
            int b = q / NG;
            int g = q - b * NG;
            int pos = g << 2;

            int lvl, local, logw;
            float strd;
            if      (pos < 16384) { lvl = 0; local = pos;         logw = 7; strd = 8.f;   }
            else if (pos < 20480) { lvl = 1; local = pos - 16384; logw = 6; strd = 16.f;  }
            else if (pos < 21504) { lvl = 2; local = pos - 20480; logw = 5; strd = 32.f;  }
            else if (pos < 21760) { lvl = 3; local = pos - 21504; logw = 4; strd = 64.f;  }
            else                  { lvl = 4; local = pos - 21760; logw = 3; strd = 128.f; }
            int hw    = 1 << (2 * logw);
            int cstep = hw >> 2;

            const float4* cls = (const float4*)(clsA[lvl] + (size_t)b * NCLS * hw + local)
                                + (size_t)(r * 20) * cstep;
            float4 bv = cls[0];
            int k0 = r * 20, k1 = k0, k2 = k0, k3 = k0;
            #pragma unroll
            for (int c = 1; c < 20; c++) {
                float4 v = cls[(size_t)c * cstep];
                int kc = r * 20 + c;
                if (v.x > bv.x) { bv.x = v.x; k0 = kc; }
                if (v.y > bv.y) { bv.y = v.y; k1 = kc; }
                if (v.z > bv.z) { bv.z = v.z; k2 = kc; }
                if (v.w > bv.w) { bv.w = v.w; k3 = kc; }
            }

            unsigned long long p0 = ((unsigned long long)__float_as_uint(bv.x) << 32) | (unsigned)(255 - k0);
            unsigned long long p1 = ((unsigned long long)__float_as_uint(bv.y) << 32) | (unsigned)(255 - k1);
            unsigned long long p2 = ((unsigned long long)__float_as_uint(bv.z) << 32) | (unsigned)(255 - k2);
            unsigned long long p3 = ((unsigned long long)__float_as_uint(bv.w) << 32) | (unsigned)(255 - k3);
            #pragma unroll
            for (int off = 1; off <= 2; off <<= 1) {
                unsigned long long qq;
                qq = __shfl_xor_sync(0xFFFFFFFFu, p0, off); if (qq > p0) p0 = qq;
                qq = __shfl_xor_sync(0xFFFFFFFFu, p1, off); if (qq > p1) p1 = qq;
                qq = __shfl_xor_sync(0xFFFFFFFFu, p2, off); if (qq > p2) p2 = qq;
                qq = __shfl_xor_sync(0xFFFFFFFFu, p3, off); if (qq > p3) p3 = qq;
            }

            if (r == 0) {
                float m0 = __uint_as_float((unsigned)(p0 >> 32));
                float m1 = __uint_as_float((unsigned)(p1 >> 32));
                float m2 = __uint_as_float((unsigned)(p2 >> 32));
                float m3 = __uint_as_float((unsigned)(p3 >> 32));
                int  c0i = 255 - (int)(p0 & 0xFFu);
                int  c1i = 255 - (int)(p1 & 0xFFu);
                int  c2i = 255 - (int)(p2 & 0xFFu);
                int  c3i = 255 - (int)(p3 & 0xFFu);

                const float4* rg = (const float4*)(regA[lvl] + (size_t)b * 4 * hw + local);
                float4 dl4 = rg[0];
                float4 dt4 = rg[cstep];
                float4 dr4 = rg[2 * cstep];
                float4 db4 = rg[3 * cstep];

                int w = 1 << logw;
                int y = local >> logw;
                int x = local & (w - 1);
                float cy = ((float)y + 0.5f) * strd;

                int o = b * NPOS + pos;
                float cx = ((float)(x + 0) + 0.5f) * strd;
                g_boxes[o + 0] = make_float4(cx - dl4.x * strd, cy - dt4.x * strd,
                                             cx + dr4.x * strd, cy + db4.x * strd);
                cx = ((float)(x + 1) + 0.5f) * strd;
                g_boxes[o + 1] = make_float4(cx - dl4.y * strd, cy - dt4.y * strd,
                                             cx + dr4.y * strd, cy + db4.y * strd);
                cx = ((float)(x + 2) + 0.5f) * strd;
                g_boxes[o + 2] = make_float4(cx - dl4.z * strd, cy - dt4.z * strd,
                                             cx + dr4.z * strd, cy + db4.z * strd);
                cx = ((float)(x + 3) + 0.5f) * strd;
                g_boxes[o + 3] = make_float4(cx - dl4.w * strd, cy - dt4.w * strd,
                                             cx + dr4.w * strd, cy + db4.w * strd);

                float s0 = (m0 > 0.05f) ? m0 : 0.0f;
                float s1 = (m1 > 0.05f) ? m1 : 0.0f;
                float s2 = (m2 > 0.05f) ? m2 : 0.0f;
                float s3 = (m3 > 0.05f) ? m3 : 0.0f;
                *(float4*)&g_score[o] = make_float4(s0, s1, s2, s3);
                *(int4*)&g_kind[o]    = make_int4(c0i, c1i, c2i, c3i);

                unsigned* hb = &g_hist[b * NBIN];
                if (s0 > 0.0f) { int bn = (int)(s0 * (float)NBIN); if (bn > NBIN-1) bn = NBIN-1; atomicAdd(&hb[bn], 1u); }
                if (s1 > 0.0f) { int bn = (int)(s1 * (float)NBIN); if (bn > NBIN-1) bn = NBIN-1; atomicAdd(&hb[bn], 1u); }
                if (s2 > 0.0f) { int bn = (int)(s2 * (float)NBIN); if (bn > NBIN-1) bn = NBIN-1; atomicAdd(&hb[bn], 1u); }
                if (s3 > 0.0f) { int bn = (int)(s3 * (float)NBIN); if (bn > NBIN-1) bn = NBIN-1; atomicAdd(&hb[bn], 1u); }
            }
        }
    }

    // ================= grid barrier (monotonic ticket, replay-safe) ===========
    __syncthreads();
    if (tid == 0) {
        __threadfence();
        unsigned long long ticket = atomicAdd(&g_arrive, 1ULL);
        if (blockIdx.x < NB) {
            unsigned long long target = (ticket / GRIDX + 1ULL) * GRIDX;
            while (*(volatile unsigned long long*)&g_arrive < target) __nanosleep(64);
            __threadfence();
        }
    }
    __syncthreads();
    if (blockIdx.x >= NB) return;

    // ================= part B: per-image select + NMS (blocks 0..7) ==========
    const int b = blockIdx.x;

    extern __shared__ char sm[];
    unsigned long long* buf      = (unsigned long long*)sm;
    unsigned long long* buf2     = (unsigned long long*)(sm + SM_BUF2);
    unsigned*           mask     = (unsigned*)(sm + SM_MASK);
    unsigned*           fineH    = (unsigned*)(sm + SM_FH);
    unsigned*           offs     = (unsigned*)(sm + SM_OFF);
    float*              sx1      = (float*)(sm + SM_X1);
    float*              sy1      = (float*)(sm + SM_Y1);
    float*              sx2      = (float*)(sm + SM_X2);
    float*              sy2      = (float*)(sm + SM_Y2);
    float*              sar      = (float*)(sm + SM_AR);
    int*                skd      = (int*)(sm + SM_KD);
    unsigned*           gsum     = (unsigned*)(sm + SM_GS);
    unsigned*           kindBits = (unsigned*)(sm + SM_KB);

    __shared__ unsigned ssum[32], sWarp[32];
    __shared__ unsigned remA[32], remB[32];
    __shared__ int s_t, s_cnt, s_changed;

    const unsigned* hb = &g_hist[b * NBIN];

    // ---- phase T: threshold bin (hist copy into smem) ----
    {
        unsigned s = 0;
        #pragma unroll
        for (int r = 0; r < 8; r++) {
            unsigned h = hb[NBIN - 1 - (8 * tid + r)];
            fineH[NBIN - 1 - (8 * tid + r)] = h;
            s += h;
        }
        gsum[tid] = s;
    }
    __syncthreads();
    if (tid < 32) {
        unsigned s = 0;
        #pragma unroll
        for (int q = 0; q < 32; q++) s += gsum[tid * 32 + q];
        ssum[tid] = s;
    }
    __syncthreads();
    if (tid == 0) {
        unsigned cum = 0;
        int t = 0;
        bool found = false;
        for (int w = 0; w < 32 && !found; w++) {
            if (cum + ssum[w] < KTOP) { cum += ssum[w]; continue; }
            for (int g = w * 32; g < w * 32 + 32 && !found; g++) {
                if (cum + gsum[g] < KTOP) { cum += gsum[g]; continue; }
                for (int r = g * 8; r < g * 8 + 8; r++) {
                    cum += fineH[NBIN - 1 - r];
                    if (cum >= KTOP) { t = NBIN - 1 - r; found = true; break; }
                }
            }
        }
        s_t = found ? t : 0;
        s_cnt = 0;
    }
    __syncthreads();
    const int   t     = s_t;
    const float lo    = (float)t * (1.0f / (float)NBIN);
    const float scale = (float)NBIN / (1.0f - lo + 1e-6f);

    // ---- phase C: zero global hist (next replay); compact + fine hist ----
    for (int i = tid; i < NBIN; i += 1024) {
        g_hist[b * NBIN + i] = 0u;
        fineH[i] = 0u;
    }
    __syncthreads();
    const float* sc_base = &g_score[b * NPOS];
    for (int i = tid; i < NPOS; i += 1024) {
        float sc = sc_base[i];
        if (sc > 0.0f) {
            int bin = (int)(sc * (float)NBIN);
            if (bin > NBIN - 1) bin = NBIN - 1;
            if (bin >= t) {
                int k = atomicAdd(&s_cnt, 1);
                if (k < CAP) {
                    buf[k] = ((unsigned long long)__float_as_uint(sc) << 32) |
                             (unsigned long long)(0xFFFFFFFFu - (unsigned)i);
                    int fb = (int)((sc - lo) * scale);
                    fb = max(0, min(NBIN - 1, fb));
                    atomicAdd(&fineH[fb], 1u);
                }
            }
        }
    }
    __syncthreads();
    const int C = min(s_cnt, CAP);

    // ---- phase S: exclusive scan over fine bins, descending ----
    unsigned c8[8];
    unsigned tsum = 0;
    #pragma unroll
    for (int r = 0; r < 8; r++) {
        int fb = NBIN - 1 - (tid * 8 + r);
        c8[r] = fineH[fb];
        tsum += c8[r];
    }
    {
        unsigned lane = tid & 31, wrp = tid >> 5;
        unsigned v = tsum;
        #pragma unroll
        for (int o = 1; o < 32; o <<= 1) {
            unsigned u = __shfl_up_sync(0xFFFFFFFFu, v, o);
            if (lane >= o) v += u;
        }
        unsigned wexcl = v - tsum;
        if (lane == 31) sWarp[wrp] = v;
        __syncthreads();
        if (tid < 32) {
            unsigned w0 = sWarp[tid];
            unsigned vv = w0;
            #pragma unroll
            for (int o = 1; o < 32; o <<= 1) {
                unsigned u = __shfl_up_sync(0xFFFFFFFFu, vv, o);
                if (tid >= (unsigned)o) vv += u;
            }
            sWarp[tid] = vv - w0;
        }
        __syncthreads();
        unsigned run = sWarp[wrp] + wexcl;
        #pragma unroll
        for (int r = 0; r < 8; r++) {
            int fb = NBIN - 1 - (tid * 8 + r);
            offs[fb] = run;
            run += c8[r];
        }
    }
    __syncthreads();

    // ---- phase X: scatter ----
    for (int k = tid; k < C; k += 1024) {
        unsigned long long key = buf[k];
        float sc = __uint_as_float((unsigned)(key >> 32));
        int fb = (int)((sc - lo) * scale);
        fb = max(0, min(NBIN - 1, fb));
        unsigned slot = atomicAdd(&offs[fb], 1u);
        buf2[slot] = key;
    }
    __syncthreads();

    // ---- phase F: intra-bin fixups; zero kindBits + row flags ----
    for (int fb = tid; fb < NBIN; fb += 1024) {
        unsigned c = fineH[fb];
        if (c >= 2) {
            unsigned st = offs[fb] - c;
            for (unsigned a = st + 1; a < st + c; a++) {
                unsigned long long kv = buf2[a];
                unsigned p = a;
                while (p > st && buf2[p - 1] < kv) { buf2[p] = buf2[p - 1]; p--; }
                buf2[p] = kv;
            }
        }
    }
    for (int i = tid; i < NCLS * 32; i += 1024) kindBits[i] = 0u;
    gsum[tid] = 0u;
    if (tid < 32) remA[tid] = 0u;
    __syncthreads();

    // ---- phase 5: emit cols 0..4, stage NMS data, class bitmasks ----
    if (tid < KTOP) {
        int i = tid;
        unsigned long long key = (i < C) ? buf2[i] : 0ULL;
        unsigned pos = 0xFFFFFFFFu - (unsigned)(key & 0xFFFFFFFFull);
        if (key == 0ULL) pos = 0;
        int src = b * NPOS + (int)pos;
        float4 bx = g_boxes[src];
        int    kd = g_kind[src];

        int row = b * KTOP + i;
        out[row * 6 + 0] = bx.x;
        out[row * 6 + 1] = bx.y;
        out[row * 6 + 2] = bx.z;
        out[row * 6 + 3] = bx.w;
        out[row * 6 + 4] = (float)kd;

        sx1[i] = bx.x; sy1[i] = bx.y; sx2[i] = bx.z; sy2[i] = bx.w;
        sar[i] = fmaxf(bx.z - bx.x, 0.0f) * fmaxf(bx.w - bx.y, 0.0f);
        skd[i] = kd;
        atomicOr(&kindBits[kd * 32 + (i >> 5)], 1u << (i & 31));
    }
    __syncthreads();

    // ---- phase 6: suppression bitmask, gated by same-class membership ----
    for (int task = tid; task < KTOP * 32; task += 1024) {
        int i = task >> 5;
        int w = task & 31;
        int kd = skd[i];
        unsigned cand = kindBits[kd * 32 + w];
        int iw = i >> 5;
        if (w < iw)       cand = 0u;
        else if (w == iw) cand &= ~((2u << (i & 31)) - 1u);
        unsigned bits = 0u;
        if (cand) {
            float x1 = sx1[i], y1 = sy1[i], x2 = sx2[i], y2 = sy2[i], ai = sar[i];
            do {
                int jj = __ffs(cand) - 1;
                cand &= cand - 1u;
                int j = w * 32 + jj;
                float xx1 = fmaxf(x1, sx1[j]);
                float yy1 = fmaxf(y1, sy1[j]);
                float xx2 = fminf(x2, sx2[j]);
                float yy2 = fminf(y2, sy2[j]);
                float inter = fmaxf(xx2 - xx1, 0.0f) * fmaxf(yy2 - yy1, 0.0f);
                float iou = inter / (((ai + sar[j]) - inter) + 1e-9f);
                if (iou > IOU_TH) bits |= (1u << jj);
            } while (cand);
        }
        mask[i * MPITCH + w] = bits;
        if (bits) gsum[i] = 1u;   // benign race: all writers store 1
    }
    __syncthreads();

    // ---- phase 8: Jacobi fixpoint (== sequential greedy on forward DAG) ----
    {
        const int wid  = tid >> 5;
        const int lane = tid & 31;
        for (int round = 0; round < KTOP; round++) {
            if (tid < 32) remB[tid] = 0u;
            if (tid == 0) s_changed = 0;
            __syncthreads();
            for (int r = wid; r < KTOP; r += 32) {
                if (gsum[r] && !((remA[r >> 5] >> (r & 31)) & 1u)) {
                    unsigned mw = mask[r * MPITCH + lane];
                    if (mw) atomicOr(&remB[lane], mw);
                }
            }
            __syncthreads();
            if (tid < 32 && remB[tid] != remA[tid]) s_changed = 1;
            __syncthreads();
            if (!s_changed) break;
            if (tid < 32) remA[tid] = remB[tid];
            __syncthreads();
        }
    }

    // ---- phase 9: final scores ----
    if (tid < KTOP) {
        int i = tid;
        bool kept = !((remA[i >> 5] >> (i & 31)) & 1u);
        float sc = (i < C) ? __uint_as_float((unsigned)(buf2[i] >> 32)) : 0.0f;
        out[(b * KTOP + i) * 6 + 5] = (kept && sc > 0.0f) ? sc : 0.0f;
    }
}

// ---------------- launch ----------------
extern "C" void kernel_launch(void* const* d_in, const int* in_sizes, int n_in,
                              void* d_out, int out_size)
{
    static const int hw[5] = { 16384, 4096, 1024, 256, 64 };
    const float* clsP[5] = { 0, 0, 0, 0, 0 };
    const float* regP[5] = { 0, 0, 0, 0, 0 };
    bool cntSeen[5] = { false, false, false, false, false };

    for (int i = 0; i < n_in; i++) {
        long long s = in_sizes[i];
        bool matched = false;
        for (int l = 0; l < 5 && !matched; l++)
            if (s == (long long)NB * NCLS * hw[l]) { clsP[l] = (const float*)d_in[i]; matched = true; }
        if (matched) continue;
        for (int l = 0; l < 5 && !matched; l++)
            if (s == (long long)NB * hw[l] && !cntSeen[l]) { cntSeen[l] = true; matched = true; }
        if (matched) continue;
        for (int l = 0; l < 5 && !matched; l++)
            if (s == (long long)NB * 4 * hw[l] && !regP[l]) { regP[l] = (const float*)d_in[i]; matched = true; }
    }

    float* out = (float*)d_out;

    cudaFuncSetAttribute(k_all, cudaFuncAttributeMaxDynamicSharedMemorySize, SMEM_BYTES);

    k_all<<<GRIDX, 1024, SMEM_BYTES>>>(clsP[0], clsP[1], clsP[2], clsP[3], clsP[4],
                                       regP[0], regP[1], regP[2], regP[3], regP[4],
                                       out);
}